// round 12
// baseline (speedup 1.0000x reference)
#include <cuda_runtime.h>
#include <cuda_bf16.h>
#include <math.h>
#include <stdint.h>

#define B_   2
#define T_   2048
#define D_   1024
#define NH_  16
#define HD_  64
#define BT_  (B_*T_)      // 4096
#define NDH_ (NH_*HD_)    // 1024
#define K2_  (D_/2)       // 512

// Scratch (allocation-free: __device__ globals)
__device__ float g_q[(size_t)B_*NH_*T_*HD_];     // [b,n,t,h]
__device__ float g_k[(size_t)B_*NH_*T_*HD_];     // [b,n,t,h]
__device__ float g_v[(size_t)B_*NH_*T_*HD_];     // [b,n,t,h]

// attention output, prepacked bf16 hi/lo pairs along (n,h): [4096][512] u32
__device__ uint32_t g_oh[(size_t)BT_*K2_], g_ol[(size_t)BT_*K2_];

// prepacked weights: [n_out][k/2] u32 = (bf16 even-k, bf16 odd-k)
__device__ uint32_t g_wq_hi[(size_t)NDH_*K2_], g_wq_lo[(size_t)NDH_*K2_];
__device__ uint32_t g_wk_hi[(size_t)NDH_*K2_], g_wk_lo[(size_t)NDH_*K2_];
__device__ uint32_t g_wv_hi[(size_t)NDH_*K2_], g_wv_lo[(size_t)NDH_*K2_];
__device__ uint32_t g_wp_hi[(size_t)D_*K2_],   g_wp_lo[(size_t)D_*K2_];

// ---------------------------------------------------------------------------
// helpers.  ldsm4 MUST be volatile: its smem read is invisible to the
// constraint list, so without volatile the compiler hoists it across the
// __syncthreads()/stores that produce the tile (round-10 correctness bug).
// mma wrappers are pure register ops -> non-volatile so ptxas can schedule.
// ---------------------------------------------------------------------------
__device__ __forceinline__ float ex2(float x) {
    float r;
    asm("ex2.approx.f32 %0, %1;" : "=f"(r) : "f"(x));
    return r;
}

__device__ __forceinline__ uint32_t smaddr(const void* p) {
    return (uint32_t)__cvta_generic_to_shared(p);
}

__device__ __forceinline__ void ldsm4(uint32_t& r0, uint32_t& r1,
                                      uint32_t& r2, uint32_t& r3, uint32_t a) {
    asm volatile("ldmatrix.sync.aligned.m8n8.x4.shared.b16 {%0,%1,%2,%3}, [%4];"
                 : "=r"(r0), "=r"(r1), "=r"(r2), "=r"(r3) : "r"(a));
}

__device__ __forceinline__ void mma_bf16(float* c,
                                         uint32_t a0, uint32_t a1, uint32_t a2, uint32_t a3,
                                         uint32_t b0, uint32_t b1) {
    asm("mma.sync.aligned.m16n8k16.row.col.f32.bf16.bf16.f32 "
        "{%0,%1,%2,%3}, {%4,%5,%6,%7}, {%8,%9}, {%0,%1,%2,%3};"
        : "+f"(c[0]), "+f"(c[1]), "+f"(c[2]), "+f"(c[3])
        : "r"(a0), "r"(a1), "r"(a2), "r"(a3), "r"(b0), "r"(b1));
}

// split two fp32 (even,odd along k) into packed bf16x2 hi and lo parts
__device__ __forceinline__ void split2(float e, float o, uint32_t& hi, uint32_t& lo) {
    __nv_bfloat162 h = __floats2bfloat162_rn(e, o);
    float he = __low2float(h), ho = __high2float(h);
    __nv_bfloat162 l = __floats2bfloat162_rn(e - he, o - ho);
    hi = *reinterpret_cast<uint32_t*>(&h);
    lo = *reinterpret_cast<uint32_t*>(&l);
}

// ---------------------------------------------------------------------------
// Prepack QKV weights W [K][N] fp32 -> hi/lo [N][K/2] u32.  z selects q/k/v.
// ---------------------------------------------------------------------------
__global__ void prepack_wqkv_kernel(const float* __restrict__ Wq,
                                    const float* __restrict__ Wk,
                                    const float* __restrict__ Wv)
{
    const int z = blockIdx.z;
    const float* W = (z == 0) ? Wq : (z == 1) ? Wk : Wv;
    uint32_t* hi = (z == 0) ? g_wq_hi : (z == 1) ? g_wk_hi : g_wv_hi;
    uint32_t* lo = (z == 0) ? g_wq_lo : (z == 1) ? g_wk_lo : g_wv_lo;
    int idx = blockIdx.x * blockDim.x + threadIdx.x;
    if (idx >= NDH_ * K2_) return;
    int kp = idx & (K2_ - 1);
    int n  = idx >> 9;
    float e = W[(size_t)(2 * kp) * NDH_ + n];
    float o = W[(size_t)(2 * kp + 1) * NDH_ + n];
    uint32_t h, l;
    split2(e, o, h, l);
    hi[(size_t)n * K2_ + kp] = h;
    lo[(size_t)n * K2_ + kp] = l;
}

// ---------------------------------------------------------------------------
// Prepack w_projection [N, D, H] -> hi/lo [d][(n,h)/2] u32
// ---------------------------------------------------------------------------
__global__ void prepack_wpt_kernel(const float* __restrict__ wp)
{
    int idx = blockIdx.x * blockDim.x + threadIdx.x;
    if (idx >= D_ * K2_) return;
    int kp = idx & (K2_ - 1);       // n*32 + hp
    int d  = idx >> 9;
    int n  = kp >> 5;
    int hp = kp & 31;
    const float* base = wp + ((size_t)n * D_ + d) * HD_ + 2 * hp;
    float e = base[0], o = base[1];
    uint32_t h, l;
    split2(e, o, h, l);
    g_wp_hi[(size_t)d * K2_ + kp] = h;
    g_wp_lo[(size_t)d * K2_ + kp] = l;
}

// ---------------------------------------------------------------------------
// bf16-split tensor-core GEMM with ldmatrix fragments (unchanged from r11).
// ---------------------------------------------------------------------------
template<int MODE, bool APACKED>
__device__ __forceinline__ void gemm_core(const float* __restrict__ A,
                                          const uint32_t* __restrict__ Ahi,
                                          const uint32_t* __restrict__ Alo,
                                          const uint32_t* __restrict__ Bhi,
                                          const uint32_t* __restrict__ Blo,
                                          const float* __restrict__ bias,
                                          float* __restrict__ C,
                                          int M, int K, int Ncols)
{
    __shared__ uint32_t AsHi[2][128 * 12];
    __shared__ uint32_t AsLo[2][128 * 12];
    __shared__ uint32_t BsHi[2][128 * 12];
    __shared__ uint32_t BsLo[2][128 * 12];

    const int tid  = threadIdx.x;
    const int warp = tid >> 5;
    const int lane = tid & 31;
    const int g    = lane >> 2;
    const int tig  = lane & 3;
    const int wm   = warp >> 2;   // 0..1  (64 rows each)
    const int wn   = warp & 3;    // 0..3  (32 cols each)
    const int m0   = blockIdx.y * 128;
    const int n0   = blockIdx.x * 128;
    const int Kp   = K >> 1;

    const int lrow  = tid >> 1;
    const int lhalf = tid & 1;

    const int arow = (lane & 7) + ((lane >> 3) & 1) * 8;
    const int akp  = (lane >> 4) * 4;
    const int brow = (lane & 7) + ((lane >> 4) & 1) * 8;
    const int bkp  = ((lane >> 3) & 1) * 4;

    const uint32_t ash = smaddr(AsHi), asl = smaddr(AsLo);
    const uint32_t bsh = smaddr(BsHi), bsl = smaddr(BsLo);
    const uint32_t a_fo = ((arow) * 12 + akp) * 4;
    const uint32_t b_fo = ((brow) * 12 + bkp) * 4;

    float acc[4][4][4];
    #pragma unroll
    for (int i = 0; i < 4; i++)
        #pragma unroll
        for (int j = 0; j < 4; j++)
            #pragma unroll
            for (int e = 0; e < 4; e++)
                acc[i][j][e] = 0.0f;

    float4 ar0, ar1;
    uint4  arh, arl;
    uint4  brh, brl;

    auto gload = [&](int k0) {
        if (APACKED) {
            const size_t aoff = (size_t)(m0 + lrow) * Kp + (k0 >> 1) + lhalf * 4;
            arh = *(const uint4*)(Ahi + aoff);
            arl = *(const uint4*)(Alo + aoff);
        } else {
            const float4* a4 = (const float4*)(A + (size_t)(m0 + lrow) * K + k0 + lhalf * 8);
            ar0 = a4[0];
            ar1 = a4[1];
        }
        const size_t boff = (size_t)(n0 + lrow) * Kp + (k0 >> 1) + lhalf * 4;
        brh = *(const uint4*)(Bhi + boff);
        brl = *(const uint4*)(Blo + boff);
    };

    auto sstore = [&](int st) {
        const int soff = lrow * 12 + lhalf * 4;
        if (APACKED) {
            *(uint4*)&AsHi[st][soff] = arh;
            *(uint4*)&AsLo[st][soff] = arl;
        } else {
            uint4 hh, ll;
            split2(ar0.x, ar0.y, hh.x, ll.x);
            split2(ar0.z, ar0.w, hh.y, ll.y);
            split2(ar1.x, ar1.y, hh.z, ll.z);
            split2(ar1.z, ar1.w, hh.w, ll.w);
            *(uint4*)&AsHi[st][soff] = hh;
            *(uint4*)&AsLo[st][soff] = ll;
        }
        *(uint4*)&BsHi[st][soff] = brh;
        *(uint4*)&BsLo[st][soff] = brl;
    };

    auto compute = [&](int st) {
        const uint32_t sto = st * (128 * 12 * 4);
        uint32_t bh[4][2], bl[4][2];
        #pragma unroll
        for (int nt2 = 0; nt2 < 2; nt2++) {
            const uint32_t ro = (wn * 32 + nt2 * 16) * 12 * 4;
            ldsm4(bh[nt2*2][0], bh[nt2*2][1], bh[nt2*2+1][0], bh[nt2*2+1][1],
                  bsh + sto + ro + b_fo);
            ldsm4(bl[nt2*2][0], bl[nt2*2][1], bl[nt2*2+1][0], bl[nt2*2+1][1],
                  bsl + sto + ro + b_fo);
        }
        #pragma unroll
        for (int mt = 0; mt < 4; mt++) {
            const uint32_t ro = (wm * 64 + mt * 16) * 12 * 4;
            uint32_t ah0, ah1, ah2, ah3, al0, al1, al2, al3;
            ldsm4(ah0, ah1, ah2, ah3, ash + sto + ro + a_fo);
            ldsm4(al0, al1, al2, al3, asl + sto + ro + a_fo);
            #pragma unroll
            for (int nt = 0; nt < 4; nt++)
                mma_bf16(acc[mt][nt], ah0, ah1, ah2, ah3, bh[nt][0], bh[nt][1]);
            #pragma unroll
            for (int nt = 0; nt < 4; nt++)
                mma_bf16(acc[mt][nt], ah0, ah1, ah2, ah3, bl[nt][0], bl[nt][1]);
            #pragma unroll
            for (int nt = 0; nt < 4; nt++)
                mma_bf16(acc[mt][nt], al0, al1, al2, al3, bh[nt][0], bh[nt][1]);
        }
    };

    gload(0);
    sstore(0);
    __syncthreads();

    int st = 0;
    for (int k0 = 16; k0 < K; k0 += 16) {
        gload(k0);
        compute(st);
        sstore(st ^ 1);
        __syncthreads();
        st ^= 1;
    }
    compute(st);

    #pragma unroll
    for (int mt = 0; mt < 4; mt++) {
        #pragma unroll
        for (int nt = 0; nt < 4; nt++) {
            const int cbase = n0 + wn * 32 + nt * 8 + tig * 2;
            #pragma unroll
            for (int e = 0; e < 4; e++) {
                const int m  = m0 + wm * 64 + mt * 16 + g + ((e >= 2) ? 8 : 0);
                const int cc = cbase + (e & 1);
                float val = acc[mt][nt][e] + bias[cc];
                if (MODE == 0) {
                    int b = m >> 11, t = m & (T_ - 1);
                    int n = cc >> 6, h = cc & 63;
                    C[(((size_t)b * NH_ + n) * T_ + t) * HD_ + h] = val;
                } else {
                    C[(size_t)m * Ncols + cc] = val;
                }
            }
        }
    }
}

// Batched QKV projection: blockIdx.z selects q / k / v
__global__ __launch_bounds__(256)
void gemm_qkv_kernel(const float* __restrict__ Aq, const float* __restrict__ Ak,
                     const float* __restrict__ Av,
                     const float* __restrict__ bq, const float* __restrict__ bk,
                     const float* __restrict__ bv,
                     float* __restrict__ Cq, float* __restrict__ Ck,
                     float* __restrict__ Cv)
{
    const int z = blockIdx.z;
    const float*    A    = (z == 0) ? Aq : (z == 1) ? Ak : Av;
    const uint32_t* Bhi  = (z == 0) ? g_wq_hi : (z == 1) ? g_wk_hi : g_wv_hi;
    const uint32_t* Blo  = (z == 0) ? g_wq_lo : (z == 1) ? g_wk_lo : g_wv_lo;
    const float*    bias = (z == 0) ? bq : (z == 1) ? bk : bv;
    float*          C    = (z == 0) ? Cq : (z == 1) ? Ck : Cv;
    gemm_core<0, false>(A, nullptr, nullptr, Bhi, Blo, bias, C, BT_, D_, NDH_);
}

__global__ __launch_bounds__(256)
void gemm_out_kernel(const float* __restrict__ bias, float* __restrict__ C)
{
    gemm_core<1, true>(nullptr, g_oh, g_ol, g_wp_hi, g_wp_lo, bias, C, BT_, NDH_, D_);
}

// ---------------------------------------------------------------------------
// bf16-split tensor-core flash attention (FA2-style: P stays in registers —
// the m16n8k16 bf16 A-fragment layout equals the C-fragment layout).
// Block = 256 threads (8 warps), 128 query rows of one (b, head); warp owns
// 16 rows. 64-key tiles. Staging (per tile):
//   KpH/KpL: [key 0..63][hp 0..31] u32 (bf16 pair along h), row stride 36
//   VpH/VpL: [keypair 0..31][h 0..63] u32 (bf16 pair along key), stride 72
// Q staged as fp32 [128][68] aliased over the same smem, consumed once.
// Dynamic smem: 9216 u32 = 36864 B -> 2 CTAs/SM (reg-limited anyway).
// Epilogue emits bf16 hi/lo packed pairs -> feeds out-proj GEMM directly.
// ---------------------------------------------------------------------------
__global__ __launch_bounds__(256, 2)
void attn_tc_kernel(const float* __restrict__ Q,
                    const float* __restrict__ K,
                    const float* __restrict__ V,
                    uint32_t* __restrict__ Ohi,
                    uint32_t* __restrict__ Olo)
{
    extern __shared__ uint32_t smu[];
    uint32_t* KpH = smu;            // 64*36 = 2304 u32
    uint32_t* KpL = smu + 2304;
    uint32_t* VpH = smu + 4608;     // 32*72 = 2304 u32
    uint32_t* VpL = smu + 6912;
    float*    Qs  = (float*)smu;    // [128][68] fp32 staging (aliased)

    const int tid  = threadIdx.x;
    const int warp = tid >> 5;
    const int lane = tid & 31;
    const int g    = lane >> 2;
    const int tig  = lane & 3;
    const int bn   = blockIdx.y;        // b*NH + n
    const int b    = bn / NH_;
    const int n    = bn % NH_;
    const int q0   = blockIdx.x * 128;
    const int wrow = warp * 16;         // 0..112

    const float* Qg = Q + ((size_t)bn * T_ + q0) * HD_;
    const float* Kg = K + (size_t)bn * T_ * HD_;
    const float* Vg = V + (size_t)bn * T_ * HD_;

    // ---- stage Q tile (128 x 64 fp32) into Qs
    #pragma unroll
    for (int i = 0; i < 8; i++) {
        int lin = tid + i * 256;          // float4 slots over 128x16
        int r = lin >> 4, c4 = (lin & 15) << 2;
        float4 v4 = *(const float4*)(Qg + r * HD_ + c4);
        Qs[r * 68 + c4 + 0] = v4.x; Qs[r * 68 + c4 + 1] = v4.y;
        Qs[r * 68 + c4 + 2] = v4.z; Qs[r * 68 + c4 + 3] = v4.w;
    }
    __syncthreads();

    // ---- persistent Q fragments, bf16 hi/lo, prescaled by 1/sqrt(H)*log2(e)
    const float qs = 0.125f * 1.4426950408889634f;
    uint32_t qh[4][4], ql[4][4];
    #pragma unroll
    for (int ks = 0; ks < 4; ks++) {
        const int r0 = (wrow + g) * 68, r1 = (wrow + g + 8) * 68;
        const int h0 = 16 * ks + 2 * tig;
        const int h1 = h0 + 8;
        split2(Qs[r0 + h0] * qs, Qs[r0 + h0 + 1] * qs, qh[ks][0], ql[ks][0]);
        split2(Qs[r1 + h0] * qs, Qs[r1 + h0 + 1] * qs, qh[ks][1], ql[ks][1]);
        split2(Qs[r0 + h1] * qs, Qs[r0 + h1 + 1] * qs, qh[ks][2], ql[ks][2]);
        split2(Qs[r1 + h1] * qs, Qs[r1 + h1 + 1] * qs, qh[ks][3], ql[ks][3]);
    }
    // loop-top __syncthreads below separates these reads from staging writes

    float of[8][4];
    #pragma unroll
    for (int i = 0; i < 8; i++)
        #pragma unroll
        for (int e = 0; e < 4; e++) of[i][e] = 0.0f;
    float m0r = -1e30f, m1r = -1e30f;
    float l0r = 0.0f,   l1r = 0.0f;

    for (int s0 = 0; s0 < T_; s0 += 64) {
        __syncthreads();   // all warps done with Qs/Kp/Vp of previous phase
        // ---- stage K: thread handles row r, 16 h (seg) -> 8 hp pairs
        {
            const int r = tid >> 2, seg = tid & 3;
            const float4* kg = (const float4*)(Kg + (size_t)(s0 + r) * HD_ + seg * 16);
            float4 k0 = kg[0], k1 = kg[1], k2 = kg[2], k3 = kg[3];
            uint4 h0v, l0v, h1v, l1v;
            split2(k0.x, k0.y, h0v.x, l0v.x); split2(k0.z, k0.w, h0v.y, l0v.y);
            split2(k1.x, k1.y, h0v.z, l0v.z); split2(k1.z, k1.w, h0v.w, l0v.w);
            split2(k2.x, k2.y, h1v.x, l1v.x); split2(k2.z, k2.w, h1v.y, l1v.y);
            split2(k3.x, k3.y, h1v.z, l1v.z); split2(k3.z, k3.w, h1v.w, l1v.w);
            const int so = r * 36 + seg * 8;
            *(uint4*)&KpH[so]     = h0v;  *(uint4*)&KpH[so + 4] = h1v;
            *(uint4*)&KpL[so]     = l0v;  *(uint4*)&KpL[so + 4] = l1v;
        }
        // ---- stage V: thread handles keypair kp, 8 h (seg)
        {
            const int kp = tid >> 3, seg = tid & 7;
            const float4* v0p = (const float4*)(Vg + (size_t)(s0 + 2 * kp)     * HD_ + seg * 8);
            const float4* v1p = (const float4*)(Vg + (size_t)(s0 + 2 * kp + 1) * HD_ + seg * 8);
            float4 a0 = v0p[0], a1 = v0p[1];
            float4 c0 = v1p[0], c1 = v1p[1];
            uint4 h0v, l0v, h1v, l1v;
            split2(a0.x, c0.x, h0v.x, l0v.x); split2(a0.y, c0.y, h0v.y, l0v.y);
            split2(a0.z, c0.z, h0v.z, l0v.z); split2(a0.w, c0.w, h0v.w, l0v.w);
            split2(a1.x, c1.x, h1v.x, l1v.x); split2(a1.y, c1.y, h1v.y, l1v.y);
            split2(a1.z, c1.z, h1v.z, l1v.z); split2(a1.w, c1.w, h1v.w, l1v.w);
            const int so = kp * 72 + seg * 8;
            *(uint4*)&VpH[so]     = h0v;  *(uint4*)&VpH[so + 4] = h1v;
            *(uint4*)&VpL[so]     = l0v;  *(uint4*)&VpL[so + 4] = l1v;
        }
        __syncthreads();

        // ---- S = (Q*qs) @ K^T ; warp computes 16x64, bf16-split (hh+hl+lh)
        float sacc[8][4];
        #pragma unroll
        for (int i = 0; i < 8; i++)
            #pragma unroll
            for (int e = 0; e < 4; e++) sacc[i][e] = 0.0f;
        #pragma unroll
        for (int ks = 0; ks < 4; ks++) {
            #pragma unroll
            for (int nt = 0; nt < 8; nt++) {
                const int base = (nt * 8 + g) * 36 + 8 * ks + tig;
                uint32_t b0h = KpH[base], b1h = KpH[base + 4];
                uint32_t b0l = KpL[base], b1l = KpL[base + 4];
                mma_bf16(sacc[nt], qh[ks][0], qh[ks][1], qh[ks][2], qh[ks][3], b0h, b1h);
                mma_bf16(sacc[nt], qh[ks][0], qh[ks][1], qh[ks][2], qh[ks][3], b0l, b1l);
                mma_bf16(sacc[nt], ql[ks][0], ql[ks][1], ql[ks][2], ql[ks][3], b0h, b1h);
            }
        }

        // ---- online softmax (base-2)
        float mx0 = -1e30f, mx1 = -1e30f;
        #pragma unroll
        for (int nt = 0; nt < 8; nt++) {
            mx0 = fmaxf(mx0, fmaxf(sacc[nt][0], sacc[nt][1]));
            mx1 = fmaxf(mx1, fmaxf(sacc[nt][2], sacc[nt][3]));
        }
        mx0 = fmaxf(mx0, __shfl_xor_sync(0xffffffffu, mx0, 1));
        mx0 = fmaxf(mx0, __shfl_xor_sync(0xffffffffu, mx0, 2));
        mx1 = fmaxf(mx1, __shfl_xor_sync(0xffffffffu, mx1, 1));
        mx1 = fmaxf(mx1, __shfl_xor_sync(0xffffffffu, mx1, 2));
        float nm0 = fmaxf(m0r, mx0), nm1 = fmaxf(m1r, mx1);
        float cr0 = ex2(m0r - nm0), cr1 = ex2(m1r - nm1);
        m0r = nm0; m1r = nm1;

        float sum0 = 0.0f, sum1 = 0.0f;
        #pragma unroll
        for (int nt = 0; nt < 8; nt++) {
            sacc[nt][0] = ex2(sacc[nt][0] - nm0);
            sacc[nt][1] = ex2(sacc[nt][1] - nm0);
            sacc[nt][2] = ex2(sacc[nt][2] - nm1);
            sacc[nt][3] = ex2(sacc[nt][3] - nm1);
            sum0 += sacc[nt][0] + sacc[nt][1];
            sum1 += sacc[nt][2] + sacc[nt][3];
        }
        sum0 += __shfl_xor_sync(0xffffffffu, sum0, 1);
        sum0 += __shfl_xor_sync(0xffffffffu, sum0, 2);
        sum1 += __shfl_xor_sync(0xffffffffu, sum1, 1);
        sum1 += __shfl_xor_sync(0xffffffffu, sum1, 2);
        l0r = l0r * cr0 + sum0;
        l1r = l1r * cr1 + sum1;
        #pragma unroll
        for (int nt = 0; nt < 8; nt++) {
            of[nt][0] *= cr0; of[nt][1] *= cr0;
            of[nt][2] *= cr1; of[nt][3] *= cr1;
        }

        // ---- O += P @ V : P converts C-frag -> A-frag in registers (no smem)
        #pragma unroll
        for (int ks = 0; ks < 4; ks++) {
            uint32_t ah0, ah1, ah2, ah3, al0, al1, al2, al3;
            split2(sacc[2*ks    ][0], sacc[2*ks    ][1], ah0, al0);
            split2(sacc[2*ks    ][2], sacc[2*ks    ][3], ah1, al1);
            split2(sacc[2*ks + 1][0], sacc[2*ks + 1][1], ah2, al2);
            split2(sacc[2*ks + 1][2], sacc[2*ks + 1][3], ah3, al3);
            #pragma unroll
            for (int ntv = 0; ntv < 8; ntv++) {
                const int vb  = (8 * ks + tig)     * 72 + ntv * 8 + g;
                const int vb2 = (8 * ks + 4 + tig) * 72 + ntv * 8 + g;
                uint32_t b0h = VpH[vb], b1h = VpH[vb2];
                uint32_t b0l = VpL[vb], b1l = VpL[vb2];
                mma_bf16(of[ntv], ah0, ah1, ah2, ah3, b0h, b1h);
                mma_bf16(of[ntv], ah0, ah1, ah2, ah3, b0l, b1l);
                mma_bf16(of[ntv], al0, al1, al2, al3, b0h, b1h);
            }
        }
    }

    // ---- epilogue: normalize, pack bf16 hi/lo pairs, write [m][(n,h)/2]
    const float inv0 = 1.0f / l0r;
    const float inv1 = 1.0f / l1r;
    const int t0 = q0 + wrow + g;
    const size_t m0row = (size_t)(b * T_ + t0) * K2_;
    const size_t m1row = (size_t)(b * T_ + t0 + 8) * K2_;
    #pragma unroll
    for (int nt = 0; nt < 8; nt++) {
        const int kp = n * 32 + nt * 4 + tig;
        uint32_t h0, l0, h1, l1;
        split2(of[nt][0] * inv0, of[nt][1] * inv0, h0, l0);
        split2(of[nt][2] * inv1, of[nt][3] * inv1, h1, l1);
        Ohi[m0row + kp] = h0;  Olo[m0row + kp] = l0;
        Ohi[m1row + kp] = h1;  Olo[m1row + kp] = l1;
    }
}

// ---------------------------------------------------------------------------
// Launch
// Inputs: 0:q 1:v 2:k 3:w_query 4:b_query 5:w_value 6:b_value 7:w_key 8:b_key
//         9:w_projection 10:b_projection
// ---------------------------------------------------------------------------
extern "C" void kernel_launch(void* const* d_in, const int* in_sizes, int n_in,
                              void* d_out, int out_size)
{
    const float* q_in = (const float*)d_in[0];
    const float* v_in = (const float*)d_in[1];
    const float* k_in = (const float*)d_in[2];
    const float* w_q  = (const float*)d_in[3];
    const float* b_q  = (const float*)d_in[4];
    const float* w_v  = (const float*)d_in[5];
    const float* b_v  = (const float*)d_in[6];
    const float* w_k  = (const float*)d_in[7];
    const float* b_k  = (const float*)d_in[8];
    const float* w_p  = (const float*)d_in[9];
    const float* b_p  = (const float*)d_in[10];
    float* out = (float*)d_out;

    float *gq, *gk, *gv;
    uint32_t *goh, *gol;
    cudaGetSymbolAddress((void**)&gq,  g_q);
    cudaGetSymbolAddress((void**)&gk,  g_k);
    cudaGetSymbolAddress((void**)&gv,  g_v);
    cudaGetSymbolAddress((void**)&goh, g_oh);
    cudaGetSymbolAddress((void**)&gol, g_ol);

    const int ATTN_SMEM = 9216 * 4;   // 36864 B (K/V bf16 tiles; Q fp32 aliased)
    cudaFuncSetAttribute(attn_tc_kernel,
                         cudaFuncAttributeMaxDynamicSharedMemorySize, ATTN_SMEM);

    // 1. prepack weights (bf16 hi/lo pairs, [n_out][k/2] layout)
    dim3 wgrid((NDH_ * K2_) / 256, 1, 3);
    prepack_wqkv_kernel<<<wgrid, 256>>>(w_q, w_k, w_v);
    prepack_wpt_kernel<<<(D_ * K2_) / 256, 256>>>(w_p);

    // 2. QKV projections, batched in one launch (grid.z selects q/k/v)
    dim3 ggrid(NDH_ / 128, BT_ / 128, 3);   // (8, 32, 3)
    gemm_qkv_kernel<<<ggrid, 256>>>(q_in, k_in, v_in, b_q, b_k, b_v, gq, gk, gv);

    // 3. attention (bf16-split flash attention, packed bf16 output)
    dim3 agrid(T_ / 128, B_ * NH_);         // (16, 32)
    attn_tc_kernel<<<agrid, 256, ATTN_SMEM>>>(gq, gk, gv, goh, gol);

    // 4. output projection (A prepacked by attention epilogue)
    dim3 pgrid(D_ / 128, BT_ / 128);        // (8, 32)
    gemm_out_kernel<<<pgrid, 256>>>(b_p, out);
}

// round 13
// speedup vs baseline: 1.0321x; 1.0321x over previous
#include <cuda_runtime.h>
#include <cuda_bf16.h>
#include <math.h>
#include <stdint.h>

#define B_   2
#define T_   2048
#define D_   1024
#define NH_  16
#define HD_  64
#define BT_  (B_*T_)      // 4096
#define NDH_ (NH_*HD_)    // 1024
#define K2_  (D_/2)       // 512
#define BN_  (B_*NH_)     // 32

// Scratch (allocation-free: __device__ globals)
__device__ float g_v[(size_t)BN_*T_*HD_];        // V fp32 [bn,t,h] (prepack input)

// packed activations: u32 = (bf16 even, bf16 odd)
__device__ uint32_t g_qp_h[(size_t)BN_*T_*32], g_qp_l[(size_t)BN_*T_*32];  // [bn][t][hp], prescaled
__device__ uint32_t g_kp_h[(size_t)BN_*T_*32], g_kp_l[(size_t)BN_*T_*32];  // [bn][t][hp]
__device__ uint32_t g_vp_h[(size_t)BN_*HD_*(T_/2)], g_vp_l[(size_t)BN_*HD_*(T_/2)]; // [bn][h][kp]

// attention output, prepacked bf16 hi/lo pairs along (n,h): [4096][512] u32
__device__ uint32_t g_oh[(size_t)BT_*K2_], g_ol[(size_t)BT_*K2_];

// prepacked weights: [n_out][k/2] u32
__device__ uint32_t g_wq_hi[(size_t)NDH_*K2_], g_wq_lo[(size_t)NDH_*K2_];
__device__ uint32_t g_wk_hi[(size_t)NDH_*K2_], g_wk_lo[(size_t)NDH_*K2_];
__device__ uint32_t g_wv_hi[(size_t)NDH_*K2_], g_wv_lo[(size_t)NDH_*K2_];
__device__ uint32_t g_wp_hi[(size_t)D_*K2_],   g_wp_lo[(size_t)D_*K2_];

#define QSCALE (0.125f * 1.4426950408889634f)

// ---------------------------------------------------------------------------
// helpers. ldsm4 MUST stay volatile (its smem read is invisible to the
// constraint list — round-10 bug). mma wrappers non-volatile (pure reg ops).
// ---------------------------------------------------------------------------
__device__ __forceinline__ float ex2(float x) {
    float r;
    asm("ex2.approx.f32 %0, %1;" : "=f"(r) : "f"(x));
    return r;
}

__device__ __forceinline__ uint32_t smaddr(const void* p) {
    return (uint32_t)__cvta_generic_to_shared(p);
}

__device__ __forceinline__ void ldsm4(uint32_t& r0, uint32_t& r1,
                                      uint32_t& r2, uint32_t& r3, uint32_t a) {
    asm volatile("ldmatrix.sync.aligned.m8n8.x4.shared.b16 {%0,%1,%2,%3}, [%4];"
                 : "=r"(r0), "=r"(r1), "=r"(r2), "=r"(r3) : "r"(a));
}

__device__ __forceinline__ void mma_bf16(float* c,
                                         uint32_t a0, uint32_t a1, uint32_t a2, uint32_t a3,
                                         uint32_t b0, uint32_t b1) {
    asm("mma.sync.aligned.m16n8k16.row.col.f32.bf16.bf16.f32 "
        "{%0,%1,%2,%3}, {%4,%5,%6,%7}, {%8,%9}, {%0,%1,%2,%3};"
        : "+f"(c[0]), "+f"(c[1]), "+f"(c[2]), "+f"(c[3])
        : "r"(a0), "r"(a1), "r"(a2), "r"(a3), "r"(b0), "r"(b1));
}

__device__ __forceinline__ void split2(float e, float o, uint32_t& hi, uint32_t& lo) {
    __nv_bfloat162 h = __floats2bfloat162_rn(e, o);
    float he = __low2float(h), ho = __high2float(h);
    __nv_bfloat162 l = __floats2bfloat162_rn(e - he, o - ho);
    hi = *reinterpret_cast<uint32_t*>(&h);
    lo = *reinterpret_cast<uint32_t*>(&l);
}

// ---------------------------------------------------------------------------
// Prepack QKV weights W [K][N] fp32 -> hi/lo [N][K/2] u32.  z selects q/k/v.
// ---------------------------------------------------------------------------
__global__ void prepack_wqkv_kernel(const float* __restrict__ Wq,
                                    const float* __restrict__ Wk,
                                    const float* __restrict__ Wv)
{
    const int z = blockIdx.z;
    const float* W = (z == 0) ? Wq : (z == 1) ? Wk : Wv;
    uint32_t* hi = (z == 0) ? g_wq_hi : (z == 1) ? g_wk_hi : g_wv_hi;
    uint32_t* lo = (z == 0) ? g_wq_lo : (z == 1) ? g_wk_lo : g_wv_lo;
    int idx = blockIdx.x * blockDim.x + threadIdx.x;
    if (idx >= NDH_ * K2_) return;
    int kp = idx & (K2_ - 1);
    int n  = idx >> 9;
    float e = W[(size_t)(2 * kp) * NDH_ + n];
    float o = W[(size_t)(2 * kp + 1) * NDH_ + n];
    uint32_t h, l;
    split2(e, o, h, l);
    hi[(size_t)n * K2_ + kp] = h;
    lo[(size_t)n * K2_ + kp] = l;
}

// ---------------------------------------------------------------------------
// Prepack w_projection [N, D, H] -> hi/lo [d][(n,h)/2] u32
// ---------------------------------------------------------------------------
__global__ void prepack_wpt_kernel(const float* __restrict__ wp)
{
    int idx = blockIdx.x * blockDim.x + threadIdx.x;
    if (idx >= D_ * K2_) return;
    int kp = idx & (K2_ - 1);
    int d  = idx >> 9;
    int n  = kp >> 5;
    int hp = kp & 31;
    const float* base = wp + ((size_t)n * D_ + d) * HD_ + 2 * hp;
    float e = base[0], o = base[1];
    uint32_t h, l;
    split2(e, o, h, l);
    g_wp_hi[(size_t)d * K2_ + kp] = h;
    g_wp_lo[(size_t)d * K2_ + kp] = l;
}

// ---------------------------------------------------------------------------
// Prepack V: [bn][t][h] fp32 -> [bn][h][kp] u32 hi/lo (bf16 pairs along t).
// Block: one (bn, 64-t tile). Coalesced read + smem transpose + coalesced write.
// ---------------------------------------------------------------------------
__global__ __launch_bounds__(256)
void prepack_v_kernel()
{
    __shared__ float sm[64][65];
    const int bn = blockIdx.y;
    const int tt = blockIdx.x;          // t-tile of 64
    const int tid = threadIdx.x;
    const float* Vg = g_v + ((size_t)bn * T_ + tt * 64) * HD_;

    #pragma unroll
    for (int i = 0; i < 4; i++) {
        int lin = tid + i * 256;        // 1024 float4 over 64x64
        int r = lin >> 4, c4 = (lin & 15) << 2;
        float4 v = *(const float4*)(Vg + r * HD_ + c4);
        sm[r][c4 + 0] = v.x; sm[r][c4 + 1] = v.y;
        sm[r][c4 + 2] = v.z; sm[r][c4 + 3] = v.w;
    }
    __syncthreads();

    #pragma unroll
    for (int i = 0; i < 8; i++) {
        int lin = tid + i * 256;        // 2048 outputs: 64 h x 32 kp
        int h = lin >> 5, kp = lin & 31;
        float e = sm[2 * kp][h], o = sm[2 * kp + 1][h];
        uint32_t hh, ll;
        split2(e, o, hh, ll);
        size_t off = ((size_t)bn * HD_ + h) * (T_ / 2) + tt * 32 + kp;
        g_vp_h[off] = hh;
        g_vp_l[off] = ll;
    }
}

// ---------------------------------------------------------------------------
// bf16-split tensor-core GEMM with ldmatrix fragments.
// MODE 0: packed u32 out [bn][t][hp] (hi/lo, optional scale)  (Q, K)
// MODE 1: fp32 out [M][Ncols] row-major                        (out-proj)
// MODE 2: fp32 out [b,n,t,h]                                   (V)
// ---------------------------------------------------------------------------
template<int MODE, bool APACKED>
__device__ __forceinline__ void gemm_core(const float* __restrict__ A,
                                          const uint32_t* __restrict__ Ahi,
                                          const uint32_t* __restrict__ Alo,
                                          const uint32_t* __restrict__ Bhi,
                                          const uint32_t* __restrict__ Blo,
                                          const float* __restrict__ bias,
                                          float* __restrict__ C,
                                          uint32_t* __restrict__ Chi,
                                          uint32_t* __restrict__ Clo,
                                          float scale,
                                          int M, int K, int Ncols)
{
    __shared__ uint32_t AsHi[2][128 * 12];
    __shared__ uint32_t AsLo[2][128 * 12];
    __shared__ uint32_t BsHi[2][128 * 12];
    __shared__ uint32_t BsLo[2][128 * 12];

    const int tid  = threadIdx.x;
    const int warp = tid >> 5;
    const int lane = tid & 31;
    const int g    = lane >> 2;
    const int tig  = lane & 3;
    const int wm   = warp >> 2;
    const int wn   = warp & 3;
    const int m0   = blockIdx.y * 128;
    const int n0   = blockIdx.x * 128;
    const int Kp   = K >> 1;

    const int lrow  = tid >> 1;
    const int lhalf = tid & 1;

    const int arow = (lane & 7) + ((lane >> 3) & 1) * 8;
    const int akp  = (lane >> 4) * 4;
    const int brow = (lane & 7) + ((lane >> 4) & 1) * 8;
    const int bkp  = ((lane >> 3) & 1) * 4;

    const uint32_t ash = smaddr(AsHi), asl = smaddr(AsLo);
    const uint32_t bsh = smaddr(BsHi), bsl = smaddr(BsLo);
    const uint32_t a_fo = ((arow) * 12 + akp) * 4;
    const uint32_t b_fo = ((brow) * 12 + bkp) * 4;

    float acc[4][4][4];
    #pragma unroll
    for (int i = 0; i < 4; i++)
        #pragma unroll
        for (int j = 0; j < 4; j++)
            #pragma unroll
            for (int e = 0; e < 4; e++)
                acc[i][j][e] = 0.0f;

    float4 ar0, ar1;
    uint4  arh, arl;
    uint4  brh, brl;

    auto gload = [&](int k0) {
        if (APACKED) {
            const size_t aoff = (size_t)(m0 + lrow) * Kp + (k0 >> 1) + lhalf * 4;
            arh = *(const uint4*)(Ahi + aoff);
            arl = *(const uint4*)(Alo + aoff);
        } else {
            const float4* a4 = (const float4*)(A + (size_t)(m0 + lrow) * K + k0 + lhalf * 8);
            ar0 = a4[0];
            ar1 = a4[1];
        }
        const size_t boff = (size_t)(n0 + lrow) * Kp + (k0 >> 1) + lhalf * 4;
        brh = *(const uint4*)(Bhi + boff);
        brl = *(const uint4*)(Blo + boff);
    };

    auto sstore = [&](int st) {
        const int soff = lrow * 12 + lhalf * 4;
        if (APACKED) {
            *(uint4*)&AsHi[st][soff] = arh;
            *(uint4*)&AsLo[st][soff] = arl;
        } else {
            uint4 hh, ll;
            split2(ar0.x, ar0.y, hh.x, ll.x);
            split2(ar0.z, ar0.w, hh.y, ll.y);
            split2(ar1.x, ar1.y, hh.z, ll.z);
            split2(ar1.z, ar1.w, hh.w, ll.w);
            *(uint4*)&AsHi[st][soff] = hh;
            *(uint4*)&AsLo[st][soff] = ll;
        }
        *(uint4*)&BsHi[st][soff] = brh;
        *(uint4*)&BsLo[st][soff] = brl;
    };

    auto compute = [&](int st) {
        const uint32_t sto = st * (128 * 12 * 4);
        uint32_t bh[4][2], bl[4][2];
        #pragma unroll
        for (int nt2 = 0; nt2 < 2; nt2++) {
            const uint32_t ro = (wn * 32 + nt2 * 16) * 12 * 4;
            ldsm4(bh[nt2*2][0], bh[nt2*2][1], bh[nt2*2+1][0], bh[nt2*2+1][1],
                  bsh + sto + ro + b_fo);
            ldsm4(bl[nt2*2][0], bl[nt2*2][1], bl[nt2*2+1][0], bl[nt2*2+1][1],
                  bsl + sto + ro + b_fo);
        }
        #pragma unroll
        for (int mt = 0; mt < 4; mt++) {
            const uint32_t ro = (wm * 64 + mt * 16) * 12 * 4;
            uint32_t ah0, ah1, ah2, ah3, al0, al1, al2, al3;
            ldsm4(ah0, ah1, ah2, ah3, ash + sto + ro + a_fo);
            ldsm4(al0, al1, al2, al3, asl + sto + ro + a_fo);
            #pragma unroll
            for (int nt = 0; nt < 4; nt++)
                mma_bf16(acc[mt][nt], ah0, ah1, ah2, ah3, bh[nt][0], bh[nt][1]);
            #pragma unroll
            for (int nt = 0; nt < 4; nt++)
                mma_bf16(acc[mt][nt], ah0, ah1, ah2, ah3, bl[nt][0], bl[nt][1]);
            #pragma unroll
            for (int nt = 0; nt < 4; nt++)
                mma_bf16(acc[mt][nt], al0, al1, al2, al3, bh[nt][0], bh[nt][1]);
        }
    };

    gload(0);
    sstore(0);
    __syncthreads();

    int st = 0;
    for (int k0 = 16; k0 < K; k0 += 16) {
        gload(k0);
        compute(st);
        sstore(st ^ 1);
        __syncthreads();
        st ^= 1;
    }
    compute(st);

    #pragma unroll
    for (int mt = 0; mt < 4; mt++) {
        #pragma unroll
        for (int nt = 0; nt < 4; nt++) {
            const int cbase = n0 + wn * 32 + nt * 8 + tig * 2;
            const int mg = m0 + wm * 64 + mt * 16 + g;
            if (MODE == 0) {
                const int nh = cbase >> 6;
                const int hp = (cbase & 63) >> 1;
                const int b  = mg >> 11, t = mg & (T_ - 1);
                const size_t o0 = ((size_t)(b * NH_ + nh) * T_ + t) * 32 + hp;
                const size_t o1 = o0 + 8 * 32;
                uint32_t h, l;
                split2((acc[mt][nt][0] + bias[cbase])     * scale,
                       (acc[mt][nt][1] + bias[cbase + 1]) * scale, h, l);
                Chi[o0] = h;  Clo[o0] = l;
                split2((acc[mt][nt][2] + bias[cbase])     * scale,
                       (acc[mt][nt][3] + bias[cbase + 1]) * scale, h, l);
                Chi[o1] = h;  Clo[o1] = l;
            } else {
                #pragma unroll
                for (int e = 0; e < 4; e++) {
                    const int m  = mg + ((e >= 2) ? 8 : 0);
                    const int cc = cbase + (e & 1);
                    float val = acc[mt][nt][e] + bias[cc];
                    if (MODE == 2) {
                        int b = m >> 11, t = m & (T_ - 1);
                        int n = cc >> 6, h = cc & 63;
                        C[(((size_t)b * NH_ + n) * T_ + t) * HD_ + h] = val;
                    } else {
                        C[(size_t)m * Ncols + cc] = val;
                    }
                }
            }
        }
    }
}

// Batched QKV projection: z=0 Q (packed, prescaled), z=1 K (packed), z=2 V fp32
__global__ __launch_bounds__(256)
void gemm_qkv_kernel(const float* __restrict__ Aq, const float* __restrict__ Ak,
                     const float* __restrict__ Av,
                     const float* __restrict__ bq, const float* __restrict__ bk,
                     const float* __restrict__ bv)
{
    const int z = blockIdx.z;
    if (z == 0)
        gemm_core<0, false>(Aq, nullptr, nullptr, g_wq_hi, g_wq_lo, bq,
                            nullptr, g_qp_h, g_qp_l, QSCALE, BT_, D_, NDH_);
    else if (z == 1)
        gemm_core<0, false>(Ak, nullptr, nullptr, g_wk_hi, g_wk_lo, bk,
                            nullptr, g_kp_h, g_kp_l, 1.0f, BT_, D_, NDH_);
    else
        gemm_core<2, false>(Av, nullptr, nullptr, g_wv_hi, g_wv_lo, bv,
                            g_v, nullptr, nullptr, 1.0f, BT_, D_, NDH_);
}

__global__ __launch_bounds__(256)
void gemm_out_kernel(const float* __restrict__ bias, float* __restrict__ C)
{
    gemm_core<1, true>(nullptr, g_oh, g_ol, g_wp_hi, g_wp_lo, bias,
                       C, nullptr, nullptr, 1.0f, BT_, NDH_, D_);
}

// ---------------------------------------------------------------------------
// bf16-split flash attention, fully prepacked inputs + ldmatrix fragments.
// Block = 256 threads (8 warps), 128 q rows of one (b,head); warp owns 16.
// smem per 64-key tile: KpH/KpL [key][hp] stride 36; VpH/VpL [h][kp] stride 36.
// Staging = pure uint4 copies (no conversion math in the loop).
// P stays in registers (C-frag == A-frag layout). Packed bf16 output.
// ---------------------------------------------------------------------------
__global__ __launch_bounds__(256, 2)
void attn_tc_kernel()
{
    extern __shared__ uint32_t smu[];
    uint32_t* KpH = smu;            // 64*36
    uint32_t* KpL = smu + 2304;
    uint32_t* VpH = smu + 4608;     // 64*36
    uint32_t* VpL = smu + 6912;

    const int tid  = threadIdx.x;
    const int warp = tid >> 5;
    const int lane = tid & 31;
    const int g    = lane >> 2;
    const int tig  = lane & 3;
    const int bn   = blockIdx.y;
    const int b    = bn / NH_;
    const int n    = bn % NH_;
    const int q0   = blockIdx.x * 128;
    const int wrow = warp * 16;

    const uint32_t kth = smaddr(KpH), ktl = smaddr(KpL);
    const uint32_t vth = smaddr(VpH), vtl = smaddr(VpL);
    const int brow = (lane & 7) + ((lane >> 4) & 1) * 8;
    const int bkp  = ((lane >> 3) & 1) * 4;
    const uint32_t b_fo = (uint32_t)(brow * 36 + bkp) * 4;

    // ---- persistent Q fragments straight from packed global (prescaled)
    uint32_t qh[4][4], ql[4][4];
    {
        const size_t r0 = ((size_t)bn * T_ + q0 + wrow + g) * 32;
        const size_t r1 = r0 + 8 * 32;
        #pragma unroll
        for (int ks = 0; ks < 4; ks++) {
            const int hp0 = 8 * ks + tig, hp1 = hp0 + 4;
            qh[ks][0] = g_qp_h[r0 + hp0];  ql[ks][0] = g_qp_l[r0 + hp0];
            qh[ks][1] = g_qp_h[r1 + hp0];  ql[ks][1] = g_qp_l[r1 + hp0];
            qh[ks][2] = g_qp_h[r0 + hp1];  ql[ks][2] = g_qp_l[r0 + hp1];
            qh[ks][3] = g_qp_h[r1 + hp1];  ql[ks][3] = g_qp_l[r1 + hp1];
        }
    }

    const uint32_t* Kgh = g_kp_h + (size_t)bn * T_ * 32;
    const uint32_t* Kgl = g_kp_l + (size_t)bn * T_ * 32;
    const uint32_t* Vgh = g_vp_h + (size_t)bn * HD_ * (T_ / 2);
    const uint32_t* Vgl = g_vp_l + (size_t)bn * HD_ * (T_ / 2);

    float of[8][4];
    #pragma unroll
    for (int i = 0; i < 8; i++)
        #pragma unroll
        for (int e = 0; e < 4; e++) of[i][e] = 0.0f;
    float m0r = -1e30f, m1r = -1e30f;
    float l0r = 0.0f,   l1r = 0.0f;

    for (int s0 = 0; s0 < T_; s0 += 64) {
        __syncthreads();
        // ---- stage K [key][hp] and V [h][kp]: pure uint4 copies
        #pragma unroll
        for (int i = 0; i < 2; i++) {
            int idx = tid + i * 256;
            int r = idx >> 3, c4 = (idx & 7) << 2;
            *(uint4*)&KpH[r * 36 + c4] = *(const uint4*)(Kgh + (size_t)(s0 + r) * 32 + c4);
            *(uint4*)&KpL[r * 36 + c4] = *(const uint4*)(Kgl + (size_t)(s0 + r) * 32 + c4);
            *(uint4*)&VpH[r * 36 + c4] = *(const uint4*)(Vgh + (size_t)r * (T_ / 2) + (s0 >> 1) + c4);
            *(uint4*)&VpL[r * 36 + c4] = *(const uint4*)(Vgl + (size_t)r * (T_ / 2) + (s0 >> 1) + c4);
        }
        __syncthreads();

        // ---- S = Q @ K^T (3-term bf16 split), warp: 16x64
        float sacc[8][4];
        #pragma unroll
        for (int i = 0; i < 8; i++)
            #pragma unroll
            for (int e = 0; e < 4; e++) sacc[i][e] = 0.0f;
        #pragma unroll
        for (int ks = 0; ks < 4; ks++) {
            #pragma unroll
            for (int nt2 = 0; nt2 < 4; nt2++) {
                const uint32_t off = (uint32_t)(nt2 * 16 * 36 + 8 * ks) * 4;
                uint32_t b0h, b1h, b2h, b3h, b0l, b1l, b2l, b3l;
                ldsm4(b0h, b1h, b2h, b3h, kth + off + b_fo);
                ldsm4(b0l, b1l, b2l, b3l, ktl + off + b_fo);
                mma_bf16(sacc[2*nt2],   qh[ks][0], qh[ks][1], qh[ks][2], qh[ks][3], b0h, b1h);
                mma_bf16(sacc[2*nt2+1], qh[ks][0], qh[ks][1], qh[ks][2], qh[ks][3], b2h, b3h);
                mma_bf16(sacc[2*nt2],   qh[ks][0], qh[ks][1], qh[ks][2], qh[ks][3], b0l, b1l);
                mma_bf16(sacc[2*nt2+1], qh[ks][0], qh[ks][1], qh[ks][2], qh[ks][3], b2l, b3l);
                mma_bf16(sacc[2*nt2],   ql[ks][0], ql[ks][1], ql[ks][2], ql[ks][3], b0h, b1h);
                mma_bf16(sacc[2*nt2+1], ql[ks][0], ql[ks][1], ql[ks][2], ql[ks][3], b2h, b3h);
            }
        }

        // ---- online softmax (base-2; scale already folded into Q)
        float mx0 = -1e30f, mx1 = -1e30f;
        #pragma unroll
        for (int nt = 0; nt < 8; nt++) {
            mx0 = fmaxf(mx0, fmaxf(sacc[nt][0], sacc[nt][1]));
            mx1 = fmaxf(mx1, fmaxf(sacc[nt][2], sacc[nt][3]));
        }
        mx0 = fmaxf(mx0, __shfl_xor_sync(0xffffffffu, mx0, 1));
        mx0 = fmaxf(mx0, __shfl_xor_sync(0xffffffffu, mx0, 2));
        mx1 = fmaxf(mx1, __shfl_xor_sync(0xffffffffu, mx1, 1));
        mx1 = fmaxf(mx1, __shfl_xor_sync(0xffffffffu, mx1, 2));
        float nm0 = fmaxf(m0r, mx0), nm1 = fmaxf(m1r, mx1);
        float cr0 = ex2(m0r - nm0), cr1 = ex2(m1r - nm1);
        m0r = nm0; m1r = nm1;

        float sum0 = 0.0f, sum1 = 0.0f;
        #pragma unroll
        for (int nt = 0; nt < 8; nt++) {
            sacc[nt][0] = ex2(sacc[nt][0] - nm0);
            sacc[nt][1] = ex2(sacc[nt][1] - nm0);
            sacc[nt][2] = ex2(sacc[nt][2] - nm1);
            sacc[nt][3] = ex2(sacc[nt][3] - nm1);
            sum0 += sacc[nt][0] + sacc[nt][1];
            sum1 += sacc[nt][2] + sacc[nt][3];
        }
        sum0 += __shfl_xor_sync(0xffffffffu, sum0, 1);
        sum0 += __shfl_xor_sync(0xffffffffu, sum0, 2);
        sum1 += __shfl_xor_sync(0xffffffffu, sum1, 1);
        sum1 += __shfl_xor_sync(0xffffffffu, sum1, 2);
        l0r = l0r * cr0 + sum0;
        l1r = l1r * cr1 + sum1;
        #pragma unroll
        for (int nt = 0; nt < 8; nt++) {
            of[nt][0] *= cr0; of[nt][1] *= cr0;
            of[nt][2] *= cr1; of[nt][3] *= cr1;
        }

        // ---- O += P @ V : P C-frag -> A-frag in registers
        #pragma unroll
        for (int ks = 0; ks < 4; ks++) {
            uint32_t ah0, ah1, ah2, ah3, al0, al1, al2, al3;
            split2(sacc[2*ks    ][0], sacc[2*ks    ][1], ah0, al0);
            split2(sacc[2*ks    ][2], sacc[2*ks    ][3], ah1, al1);
            split2(sacc[2*ks + 1][0], sacc[2*ks + 1][1], ah2, al2);
            split2(sacc[2*ks + 1][2], sacc[2*ks + 1][3], ah3, al3);
            #pragma unroll
            for (int nt2 = 0; nt2 < 4; nt2++) {
                const uint32_t off = (uint32_t)(nt2 * 16 * 36 + 8 * ks) * 4;
                uint32_t v0h, v1h, v2h, v3h, v0l, v1l, v2l, v3l;
                ldsm4(v0h, v1h, v2h, v3h, vth + off + b_fo);
                ldsm4(v0l, v1l, v2l, v3l, vtl + off + b_fo);
                mma_bf16(of[2*nt2],   ah0, ah1, ah2, ah3, v0h, v1h);
                mma_bf16(of[2*nt2+1], ah0, ah1, ah2, ah3, v2h, v3h);
                mma_bf16(of[2*nt2],   ah0, ah1, ah2, ah3, v0l, v1l);
                mma_bf16(of[2*nt2+1], ah0, ah1, ah2, ah3, v2l, v3l);
                mma_bf16(of[2*nt2],   al0, al1, al2, al3, v0h, v1h);
                mma_bf16(of[2*nt2+1], al0, al1, al2, al3, v2h, v3h);
            }
        }
    }

    // ---- epilogue: normalize, pack bf16 hi/lo pairs, write [m][(n,h)/2]
    const float inv0 = 1.0f / l0r;
    const float inv1 = 1.0f / l1r;
    const int t0 = q0 + wrow + g;
    const size_t m0row = (size_t)(b * T_ + t0) * K2_;
    const size_t m1row = (size_t)(b * T_ + t0 + 8) * K2_;
    #pragma unroll
    for (int nt = 0; nt < 8; nt++) {
        const int kp = n * 32 + nt * 4 + tig;
        uint32_t h0, l0, h1, l1;
        split2(of[nt][0] * inv0, of[nt][1] * inv0, h0, l0);
        split2(of[nt][2] * inv1, of[nt][3] * inv1, h1, l1);
        g_oh[m0row + kp] = h0;  g_ol[m0row + kp] = l0;
        g_oh[m1row + kp] = h1;  g_ol[m1row + kp] = l1;
    }
}

// ---------------------------------------------------------------------------
// Launch
// Inputs: 0:q 1:v 2:k 3:w_query 4:b_query 5:w_value 6:b_value 7:w_key 8:b_key
//         9:w_projection 10:b_projection
// ---------------------------------------------------------------------------
extern "C" void kernel_launch(void* const* d_in, const int* in_sizes, int n_in,
                              void* d_out, int out_size)
{
    const float* q_in = (const float*)d_in[0];
    const float* v_in = (const float*)d_in[1];
    const float* k_in = (const float*)d_in[2];
    const float* w_q  = (const float*)d_in[3];
    const float* b_q  = (const float*)d_in[4];
    const float* w_v  = (const float*)d_in[5];
    const float* b_v  = (const float*)d_in[6];
    const float* w_k  = (const float*)d_in[7];
    const float* b_k  = (const float*)d_in[8];
    const float* w_p  = (const float*)d_in[9];
    const float* b_p  = (const float*)d_in[10];
    float* out = (float*)d_out;

    const int ATTN_SMEM = 9216 * 4;   // 36864 B
    cudaFuncSetAttribute(attn_tc_kernel,
                         cudaFuncAttributeMaxDynamicSharedMemorySize, ATTN_SMEM);

    // 1. prepack weights
    dim3 wgrid((NDH_ * K2_) / 256, 1, 3);
    prepack_wqkv_kernel<<<wgrid, 256>>>(w_q, w_k, w_v);
    prepack_wpt_kernel<<<(D_ * K2_) / 256, 256>>>(w_p);

    // 2. QKV projections (Q/K written packed; V fp32)
    dim3 ggrid(NDH_ / 128, BT_ / 128, 3);
    gemm_qkv_kernel<<<ggrid, 256>>>(q_in, k_in, v_in, b_q, b_k, b_v);

    // 3. prepack V (transpose to [bn][h][kp] bf16 hi/lo)
    dim3 vgrid(T_ / 64, BN_);
    prepack_v_kernel<<<vgrid, 256>>>();

    // 4. attention
    dim3 agrid(T_ / 128, BN_);
    attn_tc_kernel<<<agrid, 256, ATTN_SMEM>>>();

    // 5. output projection
    dim3 pgrid(D_ / 128, BT_ / 128);
    gemm_out_kernel<<<pgrid, 256>>>(b_p, out);
}

// round 14
// speedup vs baseline: 1.0821x; 1.0485x over previous
#include <cuda_runtime.h>
#include <cuda_bf16.h>
#include <math.h>
#include <stdint.h>

#define B_   2
#define T_   2048
#define D_   1024
#define NH_  16
#define HD_  64
#define BT_  (B_*T_)      // 4096
#define NDH_ (NH_*HD_)    // 1024
#define K2_  (D_/2)       // 512
#define BN_  (B_*NH_)     // 32

// Scratch (allocation-free: __device__ globals)
__device__ float g_qt[(size_t)BN_*T_*HD_];   // Q tf32 bits, prescaled  [bn][t][h]
__device__ float g_kt[(size_t)BN_*T_*HD_];   // K tf32 bits             [bn][t][h]
__device__ float g_v [(size_t)BN_*T_*HD_];   // V fp32                  [bn][t][h]
__device__ float g_vt[(size_t)BN_*HD_*T_];   // V^T tf32 bits           [bn][h][t]

// attention output, prepacked bf16 hi/lo pairs along (n,h): [4096][512] u32
__device__ uint32_t g_oh[(size_t)BT_*K2_], g_ol[(size_t)BT_*K2_];

// prepacked weights: [n_out][k/2] u32
__device__ uint32_t g_wq_hi[(size_t)NDH_*K2_], g_wq_lo[(size_t)NDH_*K2_];
__device__ uint32_t g_wk_hi[(size_t)NDH_*K2_], g_wk_lo[(size_t)NDH_*K2_];
__device__ uint32_t g_wv_hi[(size_t)NDH_*K2_], g_wv_lo[(size_t)NDH_*K2_];
__device__ uint32_t g_wp_hi[(size_t)D_*K2_],   g_wp_lo[(size_t)D_*K2_];

#define QSCALE (0.125f * 1.4426950408889634f)

// ---------------------------------------------------------------------------
// helpers. ldsm4 MUST stay volatile (its smem read is invisible to the
// constraint list — round-10 bug). mma wrappers non-volatile (pure reg ops).
// ---------------------------------------------------------------------------
__device__ __forceinline__ uint32_t f2tf32(float x) {
    uint32_t r;
    asm("cvt.rna.tf32.f32 %0, %1;" : "=r"(r) : "f"(x));
    return r;
}

__device__ __forceinline__ float ex2(float x) {
    float r;
    asm("ex2.approx.f32 %0, %1;" : "=f"(r) : "f"(x));
    return r;
}

__device__ __forceinline__ uint32_t smaddr(const void* p) {
    return (uint32_t)__cvta_generic_to_shared(p);
}

__device__ __forceinline__ void ldsm4(uint32_t& r0, uint32_t& r1,
                                      uint32_t& r2, uint32_t& r3, uint32_t a) {
    asm volatile("ldmatrix.sync.aligned.m8n8.x4.shared.b16 {%0,%1,%2,%3}, [%4];"
                 : "=r"(r0), "=r"(r1), "=r"(r2), "=r"(r3) : "r"(a));
}

__device__ __forceinline__ void mma_tf32(float* c,
                                         uint32_t a0, uint32_t a1, uint32_t a2, uint32_t a3,
                                         uint32_t b0, uint32_t b1) {
    asm("mma.sync.aligned.m16n8k8.row.col.f32.tf32.tf32.f32 "
        "{%0,%1,%2,%3}, {%4,%5,%6,%7}, {%8,%9}, {%0,%1,%2,%3};"
        : "+f"(c[0]), "+f"(c[1]), "+f"(c[2]), "+f"(c[3])
        : "r"(a0), "r"(a1), "r"(a2), "r"(a3), "r"(b0), "r"(b1));
}

__device__ __forceinline__ void mma_bf16(float* c,
                                         uint32_t a0, uint32_t a1, uint32_t a2, uint32_t a3,
                                         uint32_t b0, uint32_t b1) {
    asm("mma.sync.aligned.m16n8k16.row.col.f32.bf16.bf16.f32 "
        "{%0,%1,%2,%3}, {%4,%5,%6,%7}, {%8,%9}, {%0,%1,%2,%3};"
        : "+f"(c[0]), "+f"(c[1]), "+f"(c[2]), "+f"(c[3])
        : "r"(a0), "r"(a1), "r"(a2), "r"(a3), "r"(b0), "r"(b1));
}

__device__ __forceinline__ void split2(float e, float o, uint32_t& hi, uint32_t& lo) {
    __nv_bfloat162 h = __floats2bfloat162_rn(e, o);
    float he = __low2float(h), ho = __high2float(h);
    __nv_bfloat162 l = __floats2bfloat162_rn(e - he, o - ho);
    hi = *reinterpret_cast<uint32_t*>(&h);
    lo = *reinterpret_cast<uint32_t*>(&l);
}

// ---------------------------------------------------------------------------
// Prepack QKV weights W [K][N] fp32 -> hi/lo [N][K/2] u32.  z selects q/k/v.
// ---------------------------------------------------------------------------
__global__ void prepack_wqkv_kernel(const float* __restrict__ Wq,
                                    const float* __restrict__ Wk,
                                    const float* __restrict__ Wv)
{
    const int z = blockIdx.z;
    const float* W = (z == 0) ? Wq : (z == 1) ? Wk : Wv;
    uint32_t* hi = (z == 0) ? g_wq_hi : (z == 1) ? g_wk_hi : g_wv_hi;
    uint32_t* lo = (z == 0) ? g_wq_lo : (z == 1) ? g_wk_lo : g_wv_lo;
    int idx = blockIdx.x * blockDim.x + threadIdx.x;
    if (idx >= NDH_ * K2_) return;
    int kp = idx & (K2_ - 1);
    int n  = idx >> 9;
    float e = W[(size_t)(2 * kp) * NDH_ + n];
    float o = W[(size_t)(2 * kp + 1) * NDH_ + n];
    uint32_t h, l;
    split2(e, o, h, l);
    hi[(size_t)n * K2_ + kp] = h;
    lo[(size_t)n * K2_ + kp] = l;
}

// ---------------------------------------------------------------------------
// Prepack w_projection [N, D, H] -> hi/lo [d][(n,h)/2] u32
// ---------------------------------------------------------------------------
__global__ void prepack_wpt_kernel(const float* __restrict__ wp)
{
    int idx = blockIdx.x * blockDim.x + threadIdx.x;
    if (idx >= D_ * K2_) return;
    int kp = idx & (K2_ - 1);
    int d  = idx >> 9;
    int n  = kp >> 5;
    int hp = kp & 31;
    const float* base = wp + ((size_t)n * D_ + d) * HD_ + 2 * hp;
    float e = base[0], o = base[1];
    uint32_t h, l;
    split2(e, o, h, l);
    g_wp_hi[(size_t)d * K2_ + kp] = h;
    g_wp_lo[(size_t)d * K2_ + kp] = l;
}

// ---------------------------------------------------------------------------
// Prepack V: [bn][t][h] fp32 -> [bn][h][t] tf32 bits (transpose).
// Block: one (bn, 64-t tile). Both global sides coalesced; smem transpose.
// ---------------------------------------------------------------------------
__global__ __launch_bounds__(256)
void prepack_v_kernel()
{
    __shared__ float sm[64][65];
    const int bn = blockIdx.y;
    const int tt = blockIdx.x;          // t-tile of 64
    const int tid = threadIdx.x;
    const float* Vg = g_v + ((size_t)bn * T_ + tt * 64) * HD_;

    #pragma unroll
    for (int i = 0; i < 4; i++) {
        int lin = tid + i * 256;        // 1024 float4 over 64x64
        int r = lin >> 4, c4 = (lin & 15) << 2;
        float4 v = *(const float4*)(Vg + r * HD_ + c4);
        sm[r][c4 + 0] = v.x; sm[r][c4 + 1] = v.y;
        sm[r][c4 + 2] = v.z; sm[r][c4 + 3] = v.w;
    }
    __syncthreads();

    #pragma unroll
    for (int i = 0; i < 4; i++) {
        int lin = tid + i * 256;        // 1024 float4 outputs: 64 h x 16 t4
        int h = lin >> 4, t4 = (lin & 15) << 2;
        float4 v;
        v.x = __uint_as_float(f2tf32(sm[t4 + 0][h]));
        v.y = __uint_as_float(f2tf32(sm[t4 + 1][h]));
        v.z = __uint_as_float(f2tf32(sm[t4 + 2][h]));
        v.w = __uint_as_float(f2tf32(sm[t4 + 3][h]));
        *(float4*)(g_vt + ((size_t)bn * HD_ + h) * T_ + tt * 64 + t4) = v;
    }
}

// ---------------------------------------------------------------------------
// bf16-split tensor-core GEMM with ldmatrix fragments.
// MODE 0: tf32 bits out [b,n,t,h], scaled    (Q with QSCALE, K with 1.0)
// MODE 1: fp32 out [M][Ncols] row-major       (out-proj)
// MODE 2: fp32 out [b,n,t,h]                  (V)
// ---------------------------------------------------------------------------
template<int MODE, bool APACKED>
__device__ __forceinline__ void gemm_core(const float* __restrict__ A,
                                          const uint32_t* __restrict__ Ahi,
                                          const uint32_t* __restrict__ Alo,
                                          const uint32_t* __restrict__ Bhi,
                                          const uint32_t* __restrict__ Blo,
                                          const float* __restrict__ bias,
                                          float* __restrict__ C,
                                          float scale,
                                          int M, int K, int Ncols)
{
    __shared__ uint32_t AsHi[2][128 * 12];
    __shared__ uint32_t AsLo[2][128 * 12];
    __shared__ uint32_t BsHi[2][128 * 12];
    __shared__ uint32_t BsLo[2][128 * 12];

    const int tid  = threadIdx.x;
    const int warp = tid >> 5;
    const int lane = tid & 31;
    const int g    = lane >> 2;
    const int tig  = lane & 3;
    const int wm   = warp >> 2;
    const int wn   = warp & 3;
    const int m0   = blockIdx.y * 128;
    const int n0   = blockIdx.x * 128;
    const int Kp   = K >> 1;

    const int lrow  = tid >> 1;
    const int lhalf = tid & 1;

    const int arow = (lane & 7) + ((lane >> 3) & 1) * 8;
    const int akp  = (lane >> 4) * 4;
    const int brow = (lane & 7) + ((lane >> 4) & 1) * 8;
    const int bkp  = ((lane >> 3) & 1) * 4;

    const uint32_t ash = smaddr(AsHi), asl = smaddr(AsLo);
    const uint32_t bsh = smaddr(BsHi), bsl = smaddr(BsLo);
    const uint32_t a_fo = ((arow) * 12 + akp) * 4;
    const uint32_t b_fo = ((brow) * 12 + bkp) * 4;

    float acc[4][4][4];
    #pragma unroll
    for (int i = 0; i < 4; i++)
        #pragma unroll
        for (int j = 0; j < 4; j++)
            #pragma unroll
            for (int e = 0; e < 4; e++)
                acc[i][j][e] = 0.0f;

    float4 ar0, ar1;
    uint4  arh, arl;
    uint4  brh, brl;

    auto gload = [&](int k0) {
        if (APACKED) {
            const size_t aoff = (size_t)(m0 + lrow) * Kp + (k0 >> 1) + lhalf * 4;
            arh = *(const uint4*)(Ahi + aoff);
            arl = *(const uint4*)(Alo + aoff);
        } else {
            const float4* a4 = (const float4*)(A + (size_t)(m0 + lrow) * K + k0 + lhalf * 8);
            ar0 = a4[0];
            ar1 = a4[1];
        }
        const size_t boff = (size_t)(n0 + lrow) * Kp + (k0 >> 1) + lhalf * 4;
        brh = *(const uint4*)(Bhi + boff);
        brl = *(const uint4*)(Blo + boff);
    };

    auto sstore = [&](int st) {
        const int soff = lrow * 12 + lhalf * 4;
        if (APACKED) {
            *(uint4*)&AsHi[st][soff] = arh;
            *(uint4*)&AsLo[st][soff] = arl;
        } else {
            uint4 hh, ll;
            split2(ar0.x, ar0.y, hh.x, ll.x);
            split2(ar0.z, ar0.w, hh.y, ll.y);
            split2(ar1.x, ar1.y, hh.z, ll.z);
            split2(ar1.z, ar1.w, hh.w, ll.w);
            *(uint4*)&AsHi[st][soff] = hh;
            *(uint4*)&AsLo[st][soff] = ll;
        }
        *(uint4*)&BsHi[st][soff] = brh;
        *(uint4*)&BsLo[st][soff] = brl;
    };

    auto compute = [&](int st) {
        const uint32_t sto = st * (128 * 12 * 4);
        uint32_t bh[4][2], bl[4][2];
        #pragma unroll
        for (int nt2 = 0; nt2 < 2; nt2++) {
            const uint32_t ro = (wn * 32 + nt2 * 16) * 12 * 4;
            ldsm4(bh[nt2*2][0], bh[nt2*2][1], bh[nt2*2+1][0], bh[nt2*2+1][1],
                  bsh + sto + ro + b_fo);
            ldsm4(bl[nt2*2][0], bl[nt2*2][1], bl[nt2*2+1][0], bl[nt2*2+1][1],
                  bsl + sto + ro + b_fo);
        }
        #pragma unroll
        for (int mt = 0; mt < 4; mt++) {
            const uint32_t ro = (wm * 64 + mt * 16) * 12 * 4;
            uint32_t ah0, ah1, ah2, ah3, al0, al1, al2, al3;
            ldsm4(ah0, ah1, ah2, ah3, ash + sto + ro + a_fo);
            ldsm4(al0, al1, al2, al3, asl + sto + ro + a_fo);
            #pragma unroll
            for (int nt = 0; nt < 4; nt++)
                mma_bf16(acc[mt][nt], ah0, ah1, ah2, ah3, bh[nt][0], bh[nt][1]);
            #pragma unroll
            for (int nt = 0; nt < 4; nt++)
                mma_bf16(acc[mt][nt], ah0, ah1, ah2, ah3, bl[nt][0], bl[nt][1]);
            #pragma unroll
            for (int nt = 0; nt < 4; nt++)
                mma_bf16(acc[mt][nt], al0, al1, al2, al3, bh[nt][0], bh[nt][1]);
        }
    };

    gload(0);
    sstore(0);
    __syncthreads();

    int st = 0;
    for (int k0 = 16; k0 < K; k0 += 16) {
        gload(k0);
        compute(st);
        sstore(st ^ 1);
        __syncthreads();
        st ^= 1;
    }
    compute(st);

    #pragma unroll
    for (int mt = 0; mt < 4; mt++) {
        #pragma unroll
        for (int nt = 0; nt < 4; nt++) {
            const int cbase = n0 + wn * 32 + nt * 8 + tig * 2;
            const int mg = m0 + wm * 64 + mt * 16 + g;
            #pragma unroll
            for (int e = 0; e < 4; e++) {
                const int m  = mg + ((e >= 2) ? 8 : 0);
                const int cc = cbase + (e & 1);
                float val = acc[mt][nt][e] + bias[cc];
                if (MODE == 0) {
                    int b = m >> 11, t = m & (T_ - 1);
                    int n = cc >> 6, h = cc & 63;
                    C[(((size_t)b * NH_ + n) * T_ + t) * HD_ + h] =
                        __uint_as_float(f2tf32(val * scale));
                } else if (MODE == 2) {
                    int b = m >> 11, t = m & (T_ - 1);
                    int n = cc >> 6, h = cc & 63;
                    C[(((size_t)b * NH_ + n) * T_ + t) * HD_ + h] = val;
                } else {
                    C[(size_t)m * Ncols + cc] = val;
                }
            }
        }
    }
}

// Batched QKV projection: z=0 Q (tf32 bits, prescaled), z=1 K (tf32 bits), z=2 V fp32
__global__ __launch_bounds__(256)
void gemm_qkv_kernel(const float* __restrict__ Aq, const float* __restrict__ Ak,
                     const float* __restrict__ Av,
                     const float* __restrict__ bq, const float* __restrict__ bk,
                     const float* __restrict__ bv)
{
    const int z = blockIdx.z;
    if (z == 0)
        gemm_core<0, false>(Aq, nullptr, nullptr, g_wq_hi, g_wq_lo, bq,
                            g_qt, QSCALE, BT_, D_, NDH_);
    else if (z == 1)
        gemm_core<0, false>(Ak, nullptr, nullptr, g_wk_hi, g_wk_lo, bk,
                            g_kt, 1.0f, BT_, D_, NDH_);
    else
        gemm_core<2, false>(Av, nullptr, nullptr, g_wv_hi, g_wv_lo, bv,
                            g_v, 1.0f, BT_, D_, NDH_);
}

__global__ __launch_bounds__(256)
void gemm_out_kernel(const float* __restrict__ bias, float* __restrict__ C)
{
    gemm_core<1, true>(nullptr, g_oh, g_ol, g_wp_hi, g_wp_lo, bias,
                       C, 1.0f, BT_, NDH_, D_);
}

// ---------------------------------------------------------------------------
// tf32 flash attention, prepacked inputs + ldmatrix fragments everywhere.
// Block = 256 threads (8 warps), 128 q rows of one (b,head); warp owns 16.
// smem per 64-key tile: Kt [key][h] stride 68, VtT [h][key] stride 68 (tf32
// bits, pure copies from prepacked global), Pw [128 q][68] for P round-trip.
// ldmatrix.b16's "b16 pair" = one tf32 element: tf32 A/B fragment maps are
// exactly the m8n8-pair layouts (addressing proven in r8/r13 GEMM).
// Packed bf16 hi/lo output -> out-proj consumes directly.
// ---------------------------------------------------------------------------
__global__ __launch_bounds__(256, 2)
void attn_tc_kernel()
{
    extern __shared__ float smx[];
    float* Kt  = smx;                 // [64][68]
    float* VtT = smx + 64 * 68;       // [64][68]
    float* Pw  = VtT + 64 * 68;       // [128][68]

    const int tid  = threadIdx.x;
    const int warp = tid >> 5;
    const int lane = tid & 31;
    const int g    = lane >> 2;
    const int tig  = lane & 3;
    const int bn   = blockIdx.y;
    const int b    = bn / NH_;
    const int n    = bn % NH_;
    const int q0   = blockIdx.x * 128;
    const int wrow = warp * 16;

    const uint32_t kt_b = smaddr(Kt);
    const uint32_t vt_b = smaddr(VtT);
    const uint32_t pw_b = smaddr(Pw);

    // ldmatrix per-lane offsets (units: u32, row stride 68)
    const int arow = (lane & 7) + ((lane >> 3) & 1) * 8;
    const int ako  = (lane >> 4) * 4;
    const int brow = (lane & 7) + ((lane >> 4) & 1) * 8;
    const int bko  = ((lane >> 3) & 1) * 4;
    const uint32_t a_fo = (uint32_t)(arow * 68 + ako) * 4;
    const uint32_t b_fo = (uint32_t)(brow * 68 + bko) * 4;

    // ---- persistent Q fragments: direct LDG from prescaled tf32 global
    uint32_t qf[8][4];
    {
        const float* Q0 = g_qt + ((size_t)bn * T_ + q0 + wrow + g) * HD_;
        const float* Q1 = Q0 + 8 * HD_;
        #pragma unroll
        for (int k8 = 0; k8 < 8; k8++) {
            qf[k8][0] = __float_as_uint(Q0[k8 * 8 + tig    ]);
            qf[k8][1] = __float_as_uint(Q1[k8 * 8 + tig    ]);
            qf[k8][2] = __float_as_uint(Q0[k8 * 8 + tig + 4]);
            qf[k8][3] = __float_as_uint(Q1[k8 * 8 + tig + 4]);
        }
    }

    const float* Kg  = g_kt + (size_t)bn * T_ * HD_;
    const float* Vtg = g_vt + (size_t)bn * HD_ * T_;

    float of[8][4];
    #pragma unroll
    for (int i = 0; i < 8; i++)
        #pragma unroll
        for (int e = 0; e < 4; e++) of[i][e] = 0.0f;
    float m0r = -1e30f, m1r = -1e30f;
    float l0r = 0.0f,   l1r = 0.0f;

    for (int s0 = 0; s0 < T_; s0 += 64) {
        __syncthreads();
        // ---- stage K [key][h] and V^T [h][key]: pure float4 copies
        #pragma unroll
        for (int i = 0; i < 4; i++) {
            int idx = tid + i * 256;           // 1024 float4 over 64x64
            int r = idx >> 4, c4 = (idx & 15) << 2;
            *(float4*)&Kt[r * 68 + c4]  = *(const float4*)(Kg  + (size_t)(s0 + r) * HD_ + c4);
            *(float4*)&VtT[r * 68 + c4] = *(const float4*)(Vtg + (size_t)r * T_ + s0 + c4);
        }
        __syncthreads();

        // ---- S = Q @ K^T (tf32), warp: 16x64; fragments via ldmatrix
        float sacc[8][4];
        #pragma unroll
        for (int i = 0; i < 8; i++)
            #pragma unroll
            for (int e = 0; e < 4; e++) sacc[i][e] = 0.0f;
        #pragma unroll
        for (int k8 = 0; k8 < 8; k8++) {
            #pragma unroll
            for (int nt2 = 0; nt2 < 4; nt2++) {
                const uint32_t off = (uint32_t)(nt2 * 16 * 68 + k8 * 8) * 4;
                uint32_t b0, b1, b2, b3;
                ldsm4(b0, b1, b2, b3, kt_b + off + b_fo);
                mma_tf32(sacc[2*nt2],   qf[k8][0], qf[k8][1], qf[k8][2], qf[k8][3], b0, b1);
                mma_tf32(sacc[2*nt2+1], qf[k8][0], qf[k8][1], qf[k8][2], qf[k8][3], b2, b3);
            }
        }

        // ---- online softmax (base-2; scale folded into Q)
        float mx0 = -1e30f, mx1 = -1e30f;
        #pragma unroll
        for (int nt = 0; nt < 8; nt++) {
            mx0 = fmaxf(mx0, fmaxf(sacc[nt][0], sacc[nt][1]));
            mx1 = fmaxf(mx1, fmaxf(sacc[nt][2], sacc[nt][3]));
        }
        mx0 = fmaxf(mx0, __shfl_xor_sync(0xffffffffu, mx0, 1));
        mx0 = fmaxf(mx0, __shfl_xor_sync(0xffffffffu, mx0, 2));
        mx1 = fmaxf(mx1, __shfl_xor_sync(0xffffffffu, mx1, 1));
        mx1 = fmaxf(mx1, __shfl_xor_sync(0xffffffffu, mx1, 2));
        float nm0 = fmaxf(m0r, mx0), nm1 = fmaxf(m1r, mx1);
        float cr0 = ex2(m0r - nm0), cr1 = ex2(m1r - nm1);
        m0r = nm0; m1r = nm1;

        float sum0 = 0.0f, sum1 = 0.0f;
        #pragma unroll
        for (int nt = 0; nt < 8; nt++) {
            sacc[nt][0] = ex2(sacc[nt][0] - nm0);
            sacc[nt][1] = ex2(sacc[nt][1] - nm0);
            sacc[nt][2] = ex2(sacc[nt][2] - nm1);
            sacc[nt][3] = ex2(sacc[nt][3] - nm1);
            sum0 += sacc[nt][0] + sacc[nt][1];
            sum1 += sacc[nt][2] + sacc[nt][3];
        }
        sum0 += __shfl_xor_sync(0xffffffffu, sum0, 1);
        sum0 += __shfl_xor_sync(0xffffffffu, sum0, 2);
        sum1 += __shfl_xor_sync(0xffffffffu, sum1, 1);
        sum1 += __shfl_xor_sync(0xffffffffu, sum1, 2);
        l0r = l0r * cr0 + sum0;
        l1r = l1r * cr1 + sum1;
        #pragma unroll
        for (int nt = 0; nt < 8; nt++) {
            of[nt][0] *= cr0; of[nt][1] *= cr0;
            of[nt][2] *= cr1; of[nt][3] *= cr1;
        }

        // ---- store P (tf32 bits) into this warp's own rows of Pw
        #pragma unroll
        for (int nt = 0; nt < 8; nt++) {
            float2 v01, v23;
            v01.x = __uint_as_float(f2tf32(sacc[nt][0]));
            v01.y = __uint_as_float(f2tf32(sacc[nt][1]));
            v23.x = __uint_as_float(f2tf32(sacc[nt][2]));
            v23.y = __uint_as_float(f2tf32(sacc[nt][3]));
            *(float2*)&Pw[(wrow + g    ) * 68 + nt * 8 + tig * 2] = v01;
            *(float2*)&Pw[(wrow + g + 8) * 68 + nt * 8 + tig * 2] = v23;
        }
        __syncwarp();

        // ---- O += P @ V : A-frags (P) and B-frags (V^T) via ldmatrix
        #pragma unroll
        for (int k8 = 0; k8 < 8; k8++) {
            uint32_t a0, a1, a2, a3;
            ldsm4(a0, a1, a2, a3,
                  pw_b + (uint32_t)(wrow * 68 * 4) + (uint32_t)(k8 * 32) + a_fo);
            #pragma unroll
            for (int nt2 = 0; nt2 < 4; nt2++) {
                const uint32_t off = (uint32_t)(nt2 * 16 * 68 + k8 * 8) * 4;
                uint32_t v0, v1, v2, v3;
                ldsm4(v0, v1, v2, v3, vt_b + off + b_fo);
                mma_tf32(of[2*nt2],   a0, a1, a2, a3, v0, v1);
                mma_tf32(of[2*nt2+1], a0, a1, a2, a3, v2, v3);
            }
        }
    }

    // ---- epilogue: normalize, pack bf16 hi/lo pairs, write [m][(n,h)/2]
    const float inv0 = 1.0f / l0r;
    const float inv1 = 1.0f / l1r;
    const int t0 = q0 + wrow + g;
    const size_t m0row = (size_t)(b * T_ + t0) * K2_;
    const size_t m1row = (size_t)(b * T_ + t0 + 8) * K2_;
    #pragma unroll
    for (int nt = 0; nt < 8; nt++) {
        const int kp = n * 32 + nt * 4 + tig;
        uint32_t h0, l0, h1, l1;
        split2(of[nt][0] * inv0, of[nt][1] * inv0, h0, l0);
        split2(of[nt][2] * inv1, of[nt][3] * inv1, h1, l1);
        g_oh[m0row + kp] = h0;  g_ol[m0row + kp] = l0;
        g_oh[m1row + kp] = h1;  g_ol[m1row + kp] = l1;
    }
}

// ---------------------------------------------------------------------------
// Launch
// Inputs: 0:q 1:v 2:k 3:w_query 4:b_query 5:w_value 6:b_value 7:w_key 8:b_key
//         9:w_projection 10:b_projection
// ---------------------------------------------------------------------------
extern "C" void kernel_launch(void* const* d_in, const int* in_sizes, int n_in,
                              void* d_out, int out_size)
{
    const float* q_in = (const float*)d_in[0];
    const float* v_in = (const float*)d_in[1];
    const float* k_in = (const float*)d_in[2];
    const float* w_q  = (const float*)d_in[3];
    const float* b_q  = (const float*)d_in[4];
    const float* w_v  = (const float*)d_in[5];
    const float* b_v  = (const float*)d_in[6];
    const float* w_k  = (const float*)d_in[7];
    const float* b_k  = (const float*)d_in[8];
    const float* w_p  = (const float*)d_in[9];
    const float* b_p  = (const float*)d_in[10];
    float* out = (float*)d_out;

    const int ATTN_SMEM = (64 * 68 + 64 * 68 + 128 * 68) * 4;   // 69632 B
    cudaFuncSetAttribute(attn_tc_kernel,
                         cudaFuncAttributeMaxDynamicSharedMemorySize, ATTN_SMEM);

    // 1. prepack weights
    dim3 wgrid((NDH_ * K2_) / 256, 1, 3);
    prepack_wqkv_kernel<<<wgrid, 256>>>(w_q, w_k, w_v);
    prepack_wpt_kernel<<<(D_ * K2_) / 256, 256>>>(w_p);

    // 2. QKV projections (Q/K written as tf32 bits, Q prescaled; V fp32)
    dim3 ggrid(NDH_ / 128, BT_ / 128, 3);
    gemm_qkv_kernel<<<ggrid, 256>>>(q_in, k_in, v_in, b_q, b_k, b_v);

    // 3. prepack V (transpose to [bn][h][t] tf32 bits)
    dim3 vgrid(T_ / 64, BN_);
    prepack_v_kernel<<<vgrid, 256>>>();

    // 4. attention (tf32, ldmatrix fragments, packed bf16 output)
    dim3 agrid(T_ / 128, BN_);
    attn_tc_kernel<<<agrid, 256, ATTN_SMEM>>>();

    // 5. output projection
    dim3 pgrid(D_ / 128, BT_ / 128);
    gemm_out_kernel<<<pgrid, 256>>>(b_p, out);
}